// round 4
// baseline (speedup 1.0000x reference)
#include <cuda_runtime.h>

// Problem constants (fixed by setup_inputs)
#define BB      2048   // batch
#define NPATCH  196    // patches
#define DD      1024   // dino dim
#define DC      512    // clip dim

// Scratch (allocation-free rule: __device__ globals)
__device__ float g_t[(size_t)BB * DD];          // projected+tanh+normalized text emb
__device__ float g_vsel[(size_t)BB * DD];       // selected+normalized visual emb
__device__ float g_scores[(size_t)BB * NPATCH]; // per-(b,j) cosine scores

// ---------------------------------------------------------------------------
// Packed f32x2 helpers (sm_103a FFMA2 path — only reachable via PTX)
// ---------------------------------------------------------------------------
__device__ __forceinline__ unsigned long long dup2(float x) {
    unsigned long long r;
    unsigned int u = __float_as_uint(x);
    asm("mov.b64 %0, {%1, %1};" : "=l"(r) : "r"(u));
    return r;
}
__device__ __forceinline__ void fma2(unsigned long long& d,
                                     unsigned long long a,
                                     unsigned long long b) {
    asm("fma.rn.f32x2 %0, %1, %2, %0;" : "+l"(d) : "l"(a), "l"(b));
}
__device__ __forceinline__ void unpack2(unsigned long long v, float& lo, float& hi) {
    unsigned int l, h;
    asm("mov.b64 {%0, %1}, %2;" : "=r"(l), "=r"(h) : "l"(v));
    lo = __uint_as_float(l); hi = __uint_as_float(h);
}

// ---------------------------------------------------------------------------
// GEMM: C[M,N] = A[M,K] * B[N,K]^T   (both row-major, K-major contraction)
// BM=BN=128, BK=16, 256 threads, 8x8 per-thread microtile with f32x2 accum.
// Optional epilogue: C = tanh(C + bias[n])
// ---------------------------------------------------------------------------
template <bool TANH>
__global__ __launch_bounds__(256, 2)
void gemm_abt(const float* __restrict__ A, const float* __restrict__ Bm,
              const float* __restrict__ bias, float* __restrict__ C, int K)
{
    __shared__ float As[16][128];
    __shared__ float Bs[16][128];

    const int tid = threadIdx.x;
    const int bm  = blockIdx.y * 128;
    const int bn  = blockIdx.x * 128;
    const int N   = gridDim.x * 128;
    const int tx  = tid & 15;   // 0..15  -> 8 cols each
    const int ty  = tid >> 4;   // 0..15  -> 8 rows each

    // gmem tile load mapping: each thread loads 2 rows (lr, lr+64), 1 float4 each
    const int lr = tid >> 2;          // 0..63
    const int lc = (tid & 3) * 4;     // 0,4,8,12

    // acc2[i][j2] holds C columns (tx*8 + 2*j2, tx*8 + 2*j2 + 1) for row ty*8+i
    unsigned long long acc2[8][4];
#pragma unroll
    for (int i = 0; i < 8; i++)
#pragma unroll
        for (int j = 0; j < 4; j++) acc2[i][j] = 0ULL;

    const float* Aptr = A + (size_t)bm * K;
    const float* Bptr = Bm + (size_t)bn * K;

    for (int k0 = 0; k0 < K; k0 += 16) {
#pragma unroll
        for (int h = 0; h < 2; h++) {
            const int row = lr + h * 64;
            float4 a = *(const float4*)(Aptr + (size_t)row * K + k0 + lc);
            As[lc + 0][row] = a.x; As[lc + 1][row] = a.y;
            As[lc + 2][row] = a.z; As[lc + 3][row] = a.w;
            float4 b = *(const float4*)(Bptr + (size_t)row * K + k0 + lc);
            Bs[lc + 0][row] = b.x; Bs[lc + 1][row] = b.y;
            Bs[lc + 2][row] = b.z; Bs[lc + 3][row] = b.w;
        }
        __syncthreads();

#pragma unroll
        for (int k = 0; k < 16; k++) {
            float af[8];
            *(float4*)&af[0] = *(const float4*)&As[k][ty * 8];
            *(float4*)&af[4] = *(const float4*)&As[k][ty * 8 + 4];
            // B fragment directly as 4 packed f32x2 (pairs of adjacent columns)
            unsigned long long bf2[4];
            ulonglong2 b01 = *(const ulonglong2*)&Bs[k][tx * 8];
            ulonglong2 b23 = *(const ulonglong2*)&Bs[k][tx * 8 + 4];
            bf2[0] = b01.x; bf2[1] = b01.y; bf2[2] = b23.x; bf2[3] = b23.y;

            unsigned long long aa[8];
#pragma unroll
            for (int i = 0; i < 8; i++) aa[i] = dup2(af[i]);
#pragma unroll
            for (int i = 0; i < 8; i++)
#pragma unroll
                for (int j = 0; j < 4; j++)
                    fma2(acc2[i][j], aa[i], bf2[j]);
        }
        __syncthreads();
    }

    // Epilogue
#pragma unroll
    for (int i = 0; i < 8; i++) {
        float* Crow = C + (size_t)(bm + ty * 8 + i) * N + bn + tx * 8;
        float v[8];
#pragma unroll
        for (int j = 0; j < 4; j++) unpack2(acc2[i][j], v[2 * j], v[2 * j + 1]);
        if (TANH) {
#pragma unroll
            for (int j = 0; j < 8; j++) v[j] = tanhf(v[j] + bias[bn + tx * 8 + j]);
        }
        *(float4*)(Crow + 0) = make_float4(v[0], v[1], v[2], v[3]);
        *(float4*)(Crow + 4) = make_float4(v[4], v[5], v[6], v[7]);
    }
}

// ---------------------------------------------------------------------------
// In-place row L2 normalization of X[rows, DD].  One block per row.
// ---------------------------------------------------------------------------
__global__ __launch_bounds__(256)
void normalize_rows(float* __restrict__ X)
{
    const int row = blockIdx.x;
    const int tid = threadIdx.x;
    float4* p = (float4*)(X + (size_t)row * DD);
    float4 a = p[tid];
    float s = a.x * a.x + a.y * a.y + a.z * a.z + a.w * a.w;
#pragma unroll
    for (int o = 16; o; o >>= 1) s += __shfl_xor_sync(0xffffffffu, s, o);

    __shared__ float red[8];
    if ((tid & 31) == 0) red[tid >> 5] = s;
    __syncthreads();
    float tot = red[0] + red[1] + red[2] + red[3] +
                red[4] + red[5] + red[6] + red[7];
    float scale = rsqrtf(fmaxf(tot, 1e-24f));
    a.x *= scale; a.y *= scale; a.z *= scale; a.w *= scale;
    p[tid] = a;
}

// ---------------------------------------------------------------------------
// Pass 1 of max-score alignment: one WARP per (b, j).
// score[b,j] = dot(t_b, v_bj) * rsqrt(||v_bj||^2)   (cosine; t_b already unit)
// Fully parallel: 401K warps, 16 LDG.128 in flight each -> HBM roofline.
// ---------------------------------------------------------------------------
__global__ __launch_bounds__(256)
void scores_kernel(const float* __restrict__ V)
{
    const int gw   = (blockIdx.x * 256 + threadIdx.x) >> 5;
    const int lane = threadIdx.x & 31;
    if (gw >= BB * NPATCH) return;
    const int b = gw / NPATCH;
    const int j = gw - b * NPATCH;

    const float4* v = (const float4*)(V + ((size_t)b * NPATCH + j) * DD);
    const float4* t = (const float4*)(g_t + (size_t)b * DD);

    float d = 0.f, n = 0.f;
#pragma unroll
    for (int s = 0; s < 8; s++) {
        float4 a = v[lane + 32 * s];
        float4 c = t[lane + 32 * s];
        d += a.x * c.x + a.y * c.y + a.z * c.z + a.w * c.w;
        n += a.x * a.x + a.y * a.y + a.z * a.z + a.w * a.w;
    }
#pragma unroll
    for (int o = 16; o; o >>= 1) {
        d += __shfl_xor_sync(0xffffffffu, d, o);
        n += __shfl_xor_sync(0xffffffffu, n, o);
    }
    if (lane == 0)
        g_scores[gw] = d * rsqrtf(fmaxf(n, 1e-24f));
}

// ---------------------------------------------------------------------------
// Pass 2: per batch element, argmax over 196 scores (first-max tie-break,
// matching jnp.argmax), then gather + L2-normalize the selected v row.
// One block (256 threads) per b.
// ---------------------------------------------------------------------------
__global__ __launch_bounds__(256)
void select_kernel(const float* __restrict__ V)
{
    const int b   = blockIdx.x;
    const int tid = threadIdx.x;

    // --- argmax over scores[b, 0..195], prefer lowest index on ties ---
    float best = -3.402823e38f;
    int   bj   = NPATCH;  // sentinel larger than any valid index
    const float* sc = g_scores + (size_t)b * NPATCH;
    for (int j = tid; j < NPATCH; j += 256) {
        float s = sc[j];
        if (s > best || (s == best && j < bj)) { best = s; bj = j; }
    }
    // warp reduce (value desc, index asc)
#pragma unroll
    for (int o = 16; o; o >>= 1) {
        float ob = __shfl_xor_sync(0xffffffffu, best, o);
        int   oj = __shfl_xor_sync(0xffffffffu, bj, o);
        if (ob > best || (ob == best && oj < bj)) { best = ob; bj = oj; }
    }
    __shared__ float rb[8];
    __shared__ int   rj[8];
    if ((tid & 31) == 0) { rb[tid >> 5] = best; rj[tid >> 5] = bj; }
    __syncthreads();
    best = rb[0]; bj = rj[0];
#pragma unroll
    for (int w = 1; w < 8; w++) {
        float ob = rb[w]; int oj = rj[w];
        if (ob > best || (ob == best && oj < bj)) { best = ob; bj = oj; }
    }

    // --- gather + normalize selected row ---
    const float4* v = (const float4*)(V + ((size_t)b * NPATCH + bj) * DD);
    float4 a = v[tid];
    float s = a.x * a.x + a.y * a.y + a.z * a.z + a.w * a.w;
#pragma unroll
    for (int o = 16; o; o >>= 1) s += __shfl_xor_sync(0xffffffffu, s, o);
    __shared__ float rn[8];
    if ((tid & 31) == 0) rn[tid >> 5] = s;
    __syncthreads();
    float tot = rn[0] + rn[1] + rn[2] + rn[3] + rn[4] + rn[5] + rn[6] + rn[7];
    float scale = rsqrtf(fmaxf(tot, 1e-24f));
    a.x *= scale; a.y *= scale; a.z *= scale; a.w *= scale;
    ((float4*)(g_vsel + (size_t)b * DD))[tid] = a;
}

// ---------------------------------------------------------------------------
// Launch: inputs in metadata order:
//   d_in[0] visual_embedding [2048,196,1024] f32
//   d_in[1] textual_embedding [2048,512]     f32
//   d_in[2] W                 [1024,512]     f32
//   d_in[3] b                 [1024]         f32
// d_out: [2048,2048] f32
// ---------------------------------------------------------------------------
extern "C" void kernel_launch(void* const* d_in, const int* in_sizes, int n_in,
                              void* d_out, int out_size)
{
    const float* visual  = (const float*)d_in[0];
    const float* textual = (const float*)d_in[1];
    const float* W       = (const float*)d_in[2];
    const float* bias    = (const float*)d_in[3];
    float* out = (float*)d_out;

    float *t_ptr = nullptr, *vsel_ptr = nullptr;
    cudaGetSymbolAddress((void**)&t_ptr, g_t);
    cudaGetSymbolAddress((void**)&vsel_ptr, g_vsel);

    // 1) t_raw = tanh(textual @ W^T + b)   [2048,1024]
    gemm_abt<true><<<dim3(DD / 128, BB / 128), 256>>>(textual, W, bias, t_ptr, DC);
    // 2) t = l2norm(t_raw)
    normalize_rows<<<BB, 256>>>(t_ptr);
    // 3) scores for all (b,j): one warp per patch row (HBM-bound streaming)
    {
        const int nwarps  = BB * NPATCH;
        const int nblocks = (nwarps * 32 + 255) / 256;
        scores_kernel<<<nblocks, 256>>>(visual);
    }
    // 4) per-b argmax + gather + normalize
    select_kernel<<<BB, 256>>>(visual);
    // 5) out = t @ v_sel^T   [2048,2048]
    gemm_abt<false><<<dim3(BB / 128, BB / 128), 256>>>(t_ptr, vsel_ptr, nullptr, out, DD);
}

// round 6
// speedup vs baseline: 1.2849x; 1.2849x over previous
#include <cuda_runtime.h>
#include <cuda_bf16.h>
#include <cstdint>

// Problem constants (fixed by setup_inputs)
#define BB      2048   // batch
#define NPATCH  196    // patches
#define DD      1024   // dino dim
#define DC      512    // clip dim
#define KAUG    3072   // augmented K for 3-term bf16 split GEMM

// Scratch (allocation-free rule: __device__ globals)
__device__ float g_t[(size_t)BB * DD];          // projected+tanh+normalized text emb
__device__ float g_vsel[(size_t)BB * DD];       // selected+normalized visual emb
__device__ float g_scores[(size_t)BB * NPATCH]; // per-(b,j) cosine scores
__device__ __align__(16) __nv_bfloat16 g_A3[(size_t)BB * KAUG]; // [Th | Tl | Th]
__device__ __align__(16) __nv_bfloat16 g_B3[(size_t)BB * KAUG]; // [Vh | Vh | Vl]

// ---------------------------------------------------------------------------
// Packed f32x2 helpers (for GEMM1)
// ---------------------------------------------------------------------------
__device__ __forceinline__ unsigned long long dup2(float x) {
    unsigned long long r;
    unsigned int u = __float_as_uint(x);
    asm("mov.b64 %0, {%1, %1};" : "=l"(r) : "r"(u));
    return r;
}
__device__ __forceinline__ void fma2(unsigned long long& d,
                                     unsigned long long a, unsigned long long b) {
    asm("fma.rn.f32x2 %0, %1, %2, %0;" : "+l"(d) : "l"(a), "l"(b));
}
__device__ __forceinline__ void unpack2(unsigned long long v, float& lo, float& hi) {
    unsigned int l, h;
    asm("mov.b64 {%0, %1}, %2;" : "=r"(l), "=r"(h) : "l"(v));
    lo = __uint_as_float(l); hi = __uint_as_float(h);
}

// ---------------------------------------------------------------------------
// GEMM1: t_raw = tanh(textual @ W^T + b)   (FFMA2 path; K=512, small)
// ---------------------------------------------------------------------------
__global__ __launch_bounds__(256, 2)
void gemm_tanh(const float* __restrict__ A, const float* __restrict__ Bm,
               const float* __restrict__ bias, float* __restrict__ C, int K)
{
    __shared__ float As[16][128];
    __shared__ float Bs[16][128];

    const int tid = threadIdx.x;
    const int bm  = blockIdx.y * 128;
    const int bn  = blockIdx.x * 128;
    const int N   = gridDim.x * 128;
    const int tx  = tid & 15;
    const int ty  = tid >> 4;
    const int lr = tid >> 2;
    const int lc = (tid & 3) * 4;

    unsigned long long acc2[8][4];
#pragma unroll
    for (int i = 0; i < 8; i++)
#pragma unroll
        for (int j = 0; j < 4; j++) acc2[i][j] = 0ULL;

    const float* Aptr = A + (size_t)bm * K;
    const float* Bptr = Bm + (size_t)bn * K;

    for (int k0 = 0; k0 < K; k0 += 16) {
#pragma unroll
        for (int h = 0; h < 2; h++) {
            const int row = lr + h * 64;
            float4 a = *(const float4*)(Aptr + (size_t)row * K + k0 + lc);
            As[lc + 0][row] = a.x; As[lc + 1][row] = a.y;
            As[lc + 2][row] = a.z; As[lc + 3][row] = a.w;
            float4 b = *(const float4*)(Bptr + (size_t)row * K + k0 + lc);
            Bs[lc + 0][row] = b.x; Bs[lc + 1][row] = b.y;
            Bs[lc + 2][row] = b.z; Bs[lc + 3][row] = b.w;
        }
        __syncthreads();

#pragma unroll
        for (int k = 0; k < 16; k++) {
            float af[8];
            *(float4*)&af[0] = *(const float4*)&As[k][ty * 8];
            *(float4*)&af[4] = *(const float4*)&As[k][ty * 8 + 4];
            unsigned long long bf2[4];
            ulonglong2 b01 = *(const ulonglong2*)&Bs[k][tx * 8];
            ulonglong2 b23 = *(const ulonglong2*)&Bs[k][tx * 8 + 4];
            bf2[0] = b01.x; bf2[1] = b01.y; bf2[2] = b23.x; bf2[3] = b23.y;
            unsigned long long aa[8];
#pragma unroll
            for (int i = 0; i < 8; i++) aa[i] = dup2(af[i]);
#pragma unroll
            for (int i = 0; i < 8; i++)
#pragma unroll
                for (int j = 0; j < 4; j++)
                    fma2(acc2[i][j], aa[i], bf2[j]);
        }
        __syncthreads();
    }

#pragma unroll
    for (int i = 0; i < 8; i++) {
        float* Crow = C + (size_t)(bm + ty * 8 + i) * N + bn + tx * 8;
        float v[8];
#pragma unroll
        for (int j = 0; j < 4; j++) unpack2(acc2[i][j], v[2 * j], v[2 * j + 1]);
#pragma unroll
        for (int j = 0; j < 8; j++) v[j] = tanhf(v[j] + bias[bn + tx * 8 + j]);
        *(float4*)(Crow + 0) = make_float4(v[0], v[1], v[2], v[3]);
        *(float4*)(Crow + 4) = make_float4(v[4], v[5], v[6], v[7]);
    }
}

// ---------------------------------------------------------------------------
// In-place row L2 normalization of X[rows, DD].  One block per row.
// ---------------------------------------------------------------------------
__global__ __launch_bounds__(256)
void normalize_rows(float* __restrict__ X)
{
    const int row = blockIdx.x;
    const int tid = threadIdx.x;
    float4* p = (float4*)(X + (size_t)row * DD);
    float4 a = p[tid];
    float s = a.x * a.x + a.y * a.y + a.z * a.z + a.w * a.w;
#pragma unroll
    for (int o = 16; o; o >>= 1) s += __shfl_xor_sync(0xffffffffu, s, o);
    __shared__ float red[8];
    if ((tid & 31) == 0) red[tid >> 5] = s;
    __syncthreads();
    float tot = red[0] + red[1] + red[2] + red[3] +
                red[4] + red[5] + red[6] + red[7];
    float scale = rsqrtf(fmaxf(tot, 1e-24f));
    a.x *= scale; a.y *= scale; a.z *= scale; a.w *= scale;
    p[tid] = a;
}

// ---------------------------------------------------------------------------
// 3-term bf16 split prep: X[2048,1024] f32 -> Y[2048,3072] bf16.
// mode 0 (A side): segments [hi, lo, hi].  mode 1 (B side): [hi, hi, lo].
// Pairing gives ah*bh + al*bh + ah*bl  (al*bl ~ 2^-18 dropped).
// ---------------------------------------------------------------------------
__global__ __launch_bounds__(256)
void prep_split(const float* __restrict__ X, __nv_bfloat16* __restrict__ Y, int mode)
{
    const int i = blockIdx.x * 256 + threadIdx.x;   // over BB * DD/2 pairs
    const int row = i >> 9;
    const int p   = i & 511;
    float2 x = *(const float2*)(X + (size_t)row * DD + p * 2);
    __nv_bfloat16 h0 = __float2bfloat16(x.x), h1 = __float2bfloat16(x.y);
    __nv_bfloat16 l0 = __float2bfloat16(x.x - __bfloat162float(h0));
    __nv_bfloat16 l1 = __float2bfloat16(x.y - __bfloat162float(h1));
    __nv_bfloat162 hi; hi.x = h0; hi.y = h1;
    __nv_bfloat162 lo; lo.x = l0; lo.y = l1;
    __nv_bfloat162* yr = (__nv_bfloat162*)(Y + (size_t)row * KAUG);
    yr[p] = hi;
    yr[512 + p]  = mode ? hi : lo;
    yr[1024 + p] = mode ? lo : hi;
}

// ===========================================================================
// GEMM2 on tensor cores via mma.sync (arch-agnostic HMMA path):
// C[2048,2048] = A3[2048,3072] @ B3[2048,3072]^T, bf16 in, fp32 accum.
// CTA 128x128, BK=64, 8 warps (warp tile 64m x 32n), 3-stage cp.async,
// XOR-swizzled SMEM (16B chunk ^ (row&7)) -> conflict-free ldmatrix.
// ===========================================================================
#define G2_BK     64
#define G2_NT     (KAUG / G2_BK)    // 48 tiles
#define G2_STAGE  3
#define G2_TILE_B 16384u            // 128 rows * 128 bytes (one matrix)
#define G2_STAGE_B 32768u           // A + B
#define G2_SMEM   (G2_STAGE * G2_STAGE_B)  // 96 KB

__device__ __forceinline__ void cp_async16(uint32_t saddr, const void* gaddr) {
    asm volatile("cp.async.cg.shared.global [%0], [%1], 16;" :: "r"(saddr), "l"(gaddr) : "memory");
}
__device__ __forceinline__ void cp_commit() {
    asm volatile("cp.async.commit_group;" ::: "memory");
}
__device__ __forceinline__ void cp_wait2() {
    asm volatile("cp.async.wait_group 2;" ::: "memory");
}
__device__ __forceinline__ void ldm_x4(uint32_t* r, uint32_t addr) {
    asm volatile("ldmatrix.sync.aligned.m8n8.x4.shared.b16 {%0,%1,%2,%3}, [%4];"
                 : "=r"(r[0]), "=r"(r[1]), "=r"(r[2]), "=r"(r[3]) : "r"(addr));
}
__device__ __forceinline__ void mma16816(float* c, const uint32_t* a, const uint32_t* b) {
    asm volatile("mma.sync.aligned.m16n8k16.row.col.f32.bf16.bf16.f32 "
                 "{%0,%1,%2,%3}, {%4,%5,%6,%7}, {%8,%9}, {%0,%1,%2,%3};"
                 : "+f"(c[0]), "+f"(c[1]), "+f"(c[2]), "+f"(c[3])
                 : "r"(a[0]), "r"(a[1]), "r"(a[2]), "r"(a[3]), "r"(b[0]), "r"(b[1]));
}
__device__ __forceinline__ uint32_t smem_u32(const void* p) {
    uint32_t a;
    asm("{ .reg .u64 t; cvta.to.shared.u64 t, %1; cvt.u32.u64 %0, t; }" : "=r"(a) : "l"(p));
    return a;
}

__global__ __launch_bounds__(256)
void gemm2_mma(const __nv_bfloat16* __restrict__ A3,
               const __nv_bfloat16* __restrict__ B3,
               float* __restrict__ C)
{
    extern __shared__ char smem[];
    const uint32_t sbase = smem_u32(smem);
    const int tid  = threadIdx.x;
    const int lane = tid & 31;
    const int wid  = tid >> 5;
    const int wm   = wid & 1;          // 2 m-tiles of 64
    const int wn   = wid >> 1;         // 4 n-tiles of 32
    const int bm   = blockIdx.y * 128;
    const int bn   = blockIdx.x * 128;

    // ---- gmem -> smem tile loader (thread t: row t/2, 4 chunks of 16B) ----
    const int ldrow = tid >> 1;            // 0..127
    const int ldcb  = (tid & 1) * 4;       // chunk base 0 or 4
    const __nv_bfloat16* Agl = A3 + (size_t)(bm + ldrow) * KAUG;
    const __nv_bfloat16* Bgl = B3 + (size_t)(bn + ldrow) * KAUG;
    const uint32_t ldswz = ldrow * 128;    // byte row base

    auto load_tile = [&](int stage, int t) {
        const uint32_t sa = sbase + stage * G2_STAGE_B + ldswz;
        const uint32_t sb = sa + G2_TILE_B;
        const __nv_bfloat16* ga = Agl + t * G2_BK + ldcb * 8;
        const __nv_bfloat16* gb = Bgl + t * G2_BK + ldcb * 8;
#pragma unroll
        for (int j = 0; j < 4; j++) {
            const int c = ldcb + j;
            const uint32_t ph = (uint32_t)((c ^ (ldrow & 7)) << 4);
            cp_async16(sa + ph, ga + j * 8);
            cp_async16(sb + ph, gb + j * 8);
        }
    };

    // ---- prologue: fill 3 stages ----
#pragma unroll
    for (int s = 0; s < G2_STAGE; s++) { load_tile(s, s); cp_commit(); }

    float acc[4][4][4];
#pragma unroll
    for (int i = 0; i < 4; i++)
#pragma unroll
        for (int j = 0; j < 4; j++)
#pragma unroll
            for (int k = 0; k < 4; k++) acc[i][j][k] = 0.f;

    // per-lane ldmatrix row/chunk components
    const int arow = wm * 64 + (lane & 15);      // + mi*16
    const int akc  = lane >> 4;                  // + ks*2
    const int brow = wn * 32 + (lane & 7) + ((lane >> 4) << 3);  // + bp*16
    const int bkc  = (lane >> 3) & 1;            // + ks*2

    for (int t = 0; t < G2_NT; t++) {
        cp_wait2();           // oldest group (tile t) retired
        __syncthreads();

        const uint32_t sa = sbase + (t % G2_STAGE) * G2_STAGE_B;
        const uint32_t sb = sa + G2_TILE_B;

#pragma unroll
        for (int ks = 0; ks < 4; ks++) {
            uint32_t af[4][4], bf[2][4];
#pragma unroll
            for (int mi = 0; mi < 4; mi++) {
                const int r  = arow + mi * 16;
                const int kc = ks * 2 + akc;
                ldm_x4(af[mi], sa + r * 128 + (((kc ^ (r & 7))) << 4));
            }
#pragma unroll
            for (int bp = 0; bp < 2; bp++) {
                const int r  = brow + bp * 16;
                const int kc = ks * 2 + bkc;
                ldm_x4(bf[bp], sb + r * 128 + (((kc ^ (r & 7))) << 4));
            }
#pragma unroll
            for (int mi = 0; mi < 4; mi++)
#pragma unroll
                for (int nj = 0; nj < 4; nj++)
                    mma16816(acc[mi][nj], af[mi], &bf[nj >> 1][(nj & 1) * 2]);
        }

        __syncthreads();      // everyone done reading this stage
        if (t + G2_STAGE < G2_NT) load_tile(t % G2_STAGE, t + G2_STAGE);
        cp_commit();          // commit every iter (possibly empty) to keep count
    }

    // ---- epilogue ----
    const int gid = lane >> 2;       // row group 0..7
    const int tig = lane & 3;        // col pair selector
#pragma unroll
    for (int mi = 0; mi < 4; mi++) {
        const int r0 = bm + wm * 64 + mi * 16 + gid;
#pragma unroll
        for (int nj = 0; nj < 4; nj++) {
            const int col = bn + wn * 32 + nj * 8 + tig * 2;
            *(float2*)(C + (size_t)r0 * BB + col)       = make_float2(acc[mi][nj][0], acc[mi][nj][1]);
            *(float2*)(C + (size_t)(r0 + 8) * BB + col) = make_float2(acc[mi][nj][2], acc[mi][nj][3]);
        }
    }
}

// ---------------------------------------------------------------------------
// Pass 1 of max-score alignment: one WARP per (b, j).
// ---------------------------------------------------------------------------
__global__ __launch_bounds__(256)
void scores_kernel(const float* __restrict__ V)
{
    const int gw   = (blockIdx.x * 256 + threadIdx.x) >> 5;
    const int lane = threadIdx.x & 31;
    if (gw >= BB * NPATCH) return;
    const int b = gw / NPATCH;
    const int j = gw - b * NPATCH;

    const float4* v = (const float4*)(V + ((size_t)b * NPATCH + j) * DD);
    const float4* t = (const float4*)(g_t + (size_t)b * DD);

    float d = 0.f, n = 0.f;
#pragma unroll
    for (int s = 0; s < 8; s++) {
        float4 a = v[lane + 32 * s];
        float4 c = t[lane + 32 * s];
        d += a.x * c.x + a.y * c.y + a.z * c.z + a.w * c.w;
        n += a.x * a.x + a.y * a.y + a.z * a.z + a.w * a.w;
    }
#pragma unroll
    for (int o = 16; o; o >>= 1) {
        d += __shfl_xor_sync(0xffffffffu, d, o);
        n += __shfl_xor_sync(0xffffffffu, n, o);
    }
    if (lane == 0)
        g_scores[gw] = d * rsqrtf(fmaxf(n, 1e-24f));
}

// ---------------------------------------------------------------------------
// Pass 2: per-b argmax (first-max tie-break) + gather + normalize.
// ---------------------------------------------------------------------------
__global__ __launch_bounds__(256)
void select_kernel(const float* __restrict__ V)
{
    const int b   = blockIdx.x;
    const int tid = threadIdx.x;

    float best = -3.402823e38f;
    int   bj   = NPATCH;
    const float* sc = g_scores + (size_t)b * NPATCH;
    for (int j = tid; j < NPATCH; j += 256) {
        float s = sc[j];
        if (s > best || (s == best && j < bj)) { best = s; bj = j; }
    }
#pragma unroll
    for (int o = 16; o; o >>= 1) {
        float ob = __shfl_xor_sync(0xffffffffu, best, o);
        int   oj = __shfl_xor_sync(0xffffffffu, bj, o);
        if (ob > best || (ob == best && oj < bj)) { best = ob; bj = oj; }
    }
    __shared__ float rb[8];
    __shared__ int   rj[8];
    if ((tid & 31) == 0) { rb[tid >> 5] = best; rj[tid >> 5] = bj; }
    __syncthreads();
    best = rb[0]; bj = rj[0];
#pragma unroll
    for (int w = 1; w < 8; w++) {
        float ob = rb[w]; int oj = rj[w];
        if (ob > best || (ob == best && oj < bj)) { best = ob; bj = oj; }
    }

    const float4* v = (const float4*)(V + ((size_t)b * NPATCH + bj) * DD);
    float4 a = v[tid];
    float s = a.x * a.x + a.y * a.y + a.z * a.z + a.w * a.w;
#pragma unroll
    for (int o = 16; o; o >>= 1) s += __shfl_xor_sync(0xffffffffu, s, o);
    __shared__ float rn[8];
    if ((tid & 31) == 0) rn[tid >> 5] = s;
    __syncthreads();
    float tot = rn[0] + rn[1] + rn[2] + rn[3] + rn[4] + rn[5] + rn[6] + rn[7];
    float scale = rsqrtf(fmaxf(tot, 1e-24f));
    a.x *= scale; a.y *= scale; a.z *= scale; a.w *= scale;
    ((float4*)(g_vsel + (size_t)b * DD))[tid] = a;
}

// ---------------------------------------------------------------------------
// Launch.  Inputs (metadata order):
//   d_in[0] visual [2048,196,1024] f32 ; d_in[1] textual [2048,512] f32
//   d_in[2] W [1024,512] f32           ; d_in[3] b [1024] f32
// d_out: [2048,2048] f32
// ---------------------------------------------------------------------------
extern "C" void kernel_launch(void* const* d_in, const int* in_sizes, int n_in,
                              void* d_out, int out_size)
{
    const float* visual  = (const float*)d_in[0];
    const float* textual = (const float*)d_in[1];
    const float* W       = (const float*)d_in[2];
    const float* bias    = (const float*)d_in[3];
    float* out = (float*)d_out;

    float *t_ptr = nullptr, *vsel_ptr = nullptr;
    __nv_bfloat16 *a3_ptr = nullptr, *b3_ptr = nullptr;
    cudaGetSymbolAddress((void**)&t_ptr, g_t);
    cudaGetSymbolAddress((void**)&vsel_ptr, g_vsel);
    cudaGetSymbolAddress((void**)&a3_ptr, g_A3);
    cudaGetSymbolAddress((void**)&b3_ptr, g_B3);

    cudaFuncSetAttribute(gemm2_mma, cudaFuncAttributeMaxDynamicSharedMemorySize, G2_SMEM);

    // 1) t_raw = tanh(textual @ W^T + b)
    gemm_tanh<<<dim3(DD / 128, BB / 128), 256>>>(textual, W, bias, t_ptr, DC);
    // 2) t = l2norm(t_raw)
    normalize_rows<<<BB, 256>>>(t_ptr);
    // 3) split t -> A3
    prep_split<<<(BB * DD / 2) / 256, 256>>>(t_ptr, a3_ptr, 0);
    // 4) scores (HBM-bound streaming pass over V)
    {
        const int nwarps  = BB * NPATCH;
        const int nblocks = (nwarps * 32 + 255) / 256;
        scores_kernel<<<nblocks, 256>>>(visual);
    }
    // 5) per-b argmax + gather + normalize
    select_kernel<<<BB, 256>>>(visual);
    // 6) split vsel -> B3
    prep_split<<<(BB * DD / 2) / 256, 256>>>(vsel_ptr, b3_ptr, 1);
    // 7) out = t @ vsel^T on tensor cores (bf16 3-term split, fp32 accum)
    gemm2_mma<<<dim3(BB / 128, BB / 128), 256, G2_SMEM>>>(a3_ptr, b3_ptr, out);
}

// round 7
// speedup vs baseline: 1.2855x; 1.0005x over previous
#include <cuda_runtime.h>
#include <cuda_bf16.h>
#include <cstdint>

// Problem constants (fixed by setup_inputs)
#define BB      2048   // batch
#define NPATCH  196    // patches
#define DD      1024   // dino dim
#define DC      512    // clip dim
#define KAUG    3072   // augmented K for 3-term bf16 split GEMM

// Scratch (allocation-free rule: __device__ globals)
__device__ float g_t[(size_t)BB * DD];          // projected+tanh+normalized text emb
__device__ float g_vsel[(size_t)BB * DD];       // selected+normalized visual emb
__device__ float g_scores[(size_t)BB * NPATCH]; // per-(b,j) cosine scores
__device__ __align__(16) __nv_bfloat16 g_A3[(size_t)BB * KAUG]; // [Th | Tl | Th]
__device__ __align__(16) __nv_bfloat16 g_B3[(size_t)BB * KAUG]; // [Vh | Vh | Vl]

// ---------------------------------------------------------------------------
// Packed f32x2 helpers (for GEMM1)
// ---------------------------------------------------------------------------
__device__ __forceinline__ unsigned long long dup2(float x) {
    unsigned long long r;
    unsigned int u = __float_as_uint(x);
    asm("mov.b64 %0, {%1, %1};" : "=l"(r) : "r"(u));
    return r;
}
__device__ __forceinline__ void fma2(unsigned long long& d,
                                     unsigned long long a, unsigned long long b) {
    asm("fma.rn.f32x2 %0, %1, %2, %0;" : "+l"(d) : "l"(a), "l"(b));
}
__device__ __forceinline__ void unpack2(unsigned long long v, float& lo, float& hi) {
    unsigned int l, h;
    asm("mov.b64 {%0, %1}, %2;" : "=r"(l), "=r"(h) : "l"(v));
    lo = __uint_as_float(l); hi = __uint_as_float(h);
}

// ---------------------------------------------------------------------------
// GEMM1: t_raw = tanh(textual @ W^T + b)   (FFMA2 path; K=512, small)
// ---------------------------------------------------------------------------
__global__ __launch_bounds__(256, 2)
void gemm_tanh(const float* __restrict__ A, const float* __restrict__ Bm,
               const float* __restrict__ bias, float* __restrict__ C, int K)
{
    __shared__ float As[16][128];
    __shared__ float Bs[16][128];

    const int tid = threadIdx.x;
    const int bm  = blockIdx.y * 128;
    const int bn  = blockIdx.x * 128;
    const int N   = gridDim.x * 128;
    const int tx  = tid & 15;
    const int ty  = tid >> 4;
    const int lr = tid >> 2;
    const int lc = (tid & 3) * 4;

    unsigned long long acc2[8][4];
#pragma unroll
    for (int i = 0; i < 8; i++)
#pragma unroll
        for (int j = 0; j < 4; j++) acc2[i][j] = 0ULL;

    const float* Aptr = A + (size_t)bm * K;
    const float* Bptr = Bm + (size_t)bn * K;

    for (int k0 = 0; k0 < K; k0 += 16) {
#pragma unroll
        for (int h = 0; h < 2; h++) {
            const int row = lr + h * 64;
            float4 a = *(const float4*)(Aptr + (size_t)row * K + k0 + lc);
            As[lc + 0][row] = a.x; As[lc + 1][row] = a.y;
            As[lc + 2][row] = a.z; As[lc + 3][row] = a.w;
            float4 b = *(const float4*)(Bptr + (size_t)row * K + k0 + lc);
            Bs[lc + 0][row] = b.x; Bs[lc + 1][row] = b.y;
            Bs[lc + 2][row] = b.z; Bs[lc + 3][row] = b.w;
        }
        __syncthreads();

#pragma unroll
        for (int k = 0; k < 16; k++) {
            float af[8];
            *(float4*)&af[0] = *(const float4*)&As[k][ty * 8];
            *(float4*)&af[4] = *(const float4*)&As[k][ty * 8 + 4];
            unsigned long long bf2[4];
            ulonglong2 b01 = *(const ulonglong2*)&Bs[k][tx * 8];
            ulonglong2 b23 = *(const ulonglong2*)&Bs[k][tx * 8 + 4];
            bf2[0] = b01.x; bf2[1] = b01.y; bf2[2] = b23.x; bf2[3] = b23.y;
            unsigned long long aa[8];
#pragma unroll
            for (int i = 0; i < 8; i++) aa[i] = dup2(af[i]);
#pragma unroll
            for (int i = 0; i < 8; i++)
#pragma unroll
                for (int j = 0; j < 4; j++)
                    fma2(acc2[i][j], aa[i], bf2[j]);
        }
        __syncthreads();
    }

#pragma unroll
    for (int i = 0; i < 8; i++) {
        float* Crow = C + (size_t)(bm + ty * 8 + i) * N + bn + tx * 8;
        float v[8];
#pragma unroll
        for (int j = 0; j < 4; j++) unpack2(acc2[i][j], v[2 * j], v[2 * j + 1]);
#pragma unroll
        for (int j = 0; j < 8; j++) v[j] = tanhf(v[j] + bias[bn + tx * 8 + j]);
        *(float4*)(Crow + 0) = make_float4(v[0], v[1], v[2], v[3]);
        *(float4*)(Crow + 4) = make_float4(v[4], v[5], v[6], v[7]);
    }
}

// ---------------------------------------------------------------------------
// In-place row L2 normalization of X[rows, DD].  One block per row.
// ---------------------------------------------------------------------------
__global__ __launch_bounds__(256)
void normalize_rows(float* __restrict__ X)
{
    const int row = blockIdx.x;
    const int tid = threadIdx.x;
    float4* p = (float4*)(X + (size_t)row * DD);
    float4 a = p[tid];
    float s = a.x * a.x + a.y * a.y + a.z * a.z + a.w * a.w;
#pragma unroll
    for (int o = 16; o; o >>= 1) s += __shfl_xor_sync(0xffffffffu, s, o);
    __shared__ float red[8];
    if ((tid & 31) == 0) red[tid >> 5] = s;
    __syncthreads();
    float tot = red[0] + red[1] + red[2] + red[3] +
                red[4] + red[5] + red[6] + red[7];
    float scale = rsqrtf(fmaxf(tot, 1e-24f));
    a.x *= scale; a.y *= scale; a.z *= scale; a.w *= scale;
    p[tid] = a;
}

// ---------------------------------------------------------------------------
// 3-term bf16 split prep: X[2048,1024] f32 -> Y[2048,3072] bf16.
// mode 0 (A side): segments [hi, lo, hi].  mode 1 (B side): [hi, hi, lo].
// Pairing gives ah*bh + al*bh + ah*bl  (al*bl ~ 2^-18 dropped).
// ---------------------------------------------------------------------------
__global__ __launch_bounds__(256)
void prep_split(const float* __restrict__ X, __nv_bfloat16* __restrict__ Y, int mode)
{
    const int i = blockIdx.x * 256 + threadIdx.x;   // over BB * DD/2 pairs
    const int row = i >> 9;
    const int p   = i & 511;
    float2 x = *(const float2*)(X + (size_t)row * DD + p * 2);
    __nv_bfloat16 h0 = __float2bfloat16(x.x), h1 = __float2bfloat16(x.y);
    __nv_bfloat16 l0 = __float2bfloat16(x.x - __bfloat162float(h0));
    __nv_bfloat16 l1 = __float2bfloat16(x.y - __bfloat162float(h1));
    __nv_bfloat162 hi; hi.x = h0; hi.y = h1;
    __nv_bfloat162 lo; lo.x = l0; lo.y = l1;
    __nv_bfloat162* yr = (__nv_bfloat162*)(Y + (size_t)row * KAUG);
    yr[p] = hi;
    yr[512 + p]  = mode ? hi : lo;
    yr[1024 + p] = mode ? lo : hi;
}

// ===========================================================================
// GEMM2 on tensor cores via mma.sync (arch-agnostic HMMA path):
// C[2048,2048] = A3[2048,3072] @ B3[2048,3072]^T, bf16 in, fp32 accum.
// CTA 128x128, BK=64, 8 warps (warp tile 64m x 32n), 3-stage cp.async,
// XOR-swizzled SMEM (16B chunk ^ (row&7)) -> conflict-free ldmatrix.
// ===========================================================================
#define G2_BK     64
#define G2_NT     (KAUG / G2_BK)    // 48 tiles
#define G2_STAGE  3
#define G2_TILE_B 16384u            // 128 rows * 128 bytes (one matrix)
#define G2_STAGE_B 32768u           // A + B
#define G2_SMEM   (G2_STAGE * G2_STAGE_B)  // 96 KB

__device__ __forceinline__ void cp_async16(uint32_t saddr, const void* gaddr) {
    asm volatile("cp.async.cg.shared.global [%0], [%1], 16;" :: "r"(saddr), "l"(gaddr) : "memory");
}
__device__ __forceinline__ void cp_commit() {
    asm volatile("cp.async.commit_group;" ::: "memory");
}
__device__ __forceinline__ void cp_wait2() {
    asm volatile("cp.async.wait_group 2;" ::: "memory");
}
__device__ __forceinline__ void ldm_x4(uint32_t* r, uint32_t addr) {
    asm volatile("ldmatrix.sync.aligned.m8n8.x4.shared.b16 {%0,%1,%2,%3}, [%4];"
                 : "=r"(r[0]), "=r"(r[1]), "=r"(r[2]), "=r"(r[3]) : "r"(addr));
}
__device__ __forceinline__ void mma16816(float* c, const uint32_t* a, const uint32_t* b) {
    asm volatile("mma.sync.aligned.m16n8k16.row.col.f32.bf16.bf16.f32 "
                 "{%0,%1,%2,%3}, {%4,%5,%6,%7}, {%8,%9}, {%0,%1,%2,%3};"
                 : "+f"(c[0]), "+f"(c[1]), "+f"(c[2]), "+f"(c[3])
                 : "r"(a[0]), "r"(a[1]), "r"(a[2]), "r"(a[3]), "r"(b[0]), "r"(b[1]));
}
__device__ __forceinline__ uint32_t smem_u32(const void* p) {
    uint32_t a;
    asm("{ .reg .u64 t; cvta.to.shared.u64 t, %1; cvt.u32.u64 %0, t; }" : "=r"(a) : "l"(p));
    return a;
}

__global__ __launch_bounds__(256)
void gemm2_mma(const __nv_bfloat16* __restrict__ A3,
               const __nv_bfloat16* __restrict__ B3,
               float* __restrict__ C)
{
    extern __shared__ char smem[];
    const uint32_t sbase = smem_u32(smem);
    const int tid  = threadIdx.x;
    const int lane = tid & 31;
    const int wid  = tid >> 5;
    const int wm   = wid & 1;          // 2 m-tiles of 64
    const int wn   = wid >> 1;         // 4 n-tiles of 32
    const int bm   = blockIdx.y * 128;
    const int bn   = blockIdx.x * 128;

    // ---- gmem -> smem tile loader (thread t: row t/2, 4 chunks of 16B) ----
    const int ldrow = tid >> 1;            // 0..127
    const int ldcb  = (tid & 1) * 4;       // chunk base 0 or 4
    const __nv_bfloat16* Agl = A3 + (size_t)(bm + ldrow) * KAUG;
    const __nv_bfloat16* Bgl = B3 + (size_t)(bn + ldrow) * KAUG;
    const uint32_t ldswz = ldrow * 128;    // byte row base

    auto load_tile = [&](int stage, int t) {
        const uint32_t sa = sbase + stage * G2_STAGE_B + ldswz;
        const uint32_t sb = sa + G2_TILE_B;
        const __nv_bfloat16* ga = Agl + t * G2_BK + ldcb * 8;
        const __nv_bfloat16* gb = Bgl + t * G2_BK + ldcb * 8;
#pragma unroll
        for (int j = 0; j < 4; j++) {
            const int c = ldcb + j;
            const uint32_t ph = (uint32_t)((c ^ (ldrow & 7)) << 4);
            cp_async16(sa + ph, ga + j * 8);
            cp_async16(sb + ph, gb + j * 8);
        }
    };

    // ---- prologue: fill 3 stages ----
#pragma unroll
    for (int s = 0; s < G2_STAGE; s++) { load_tile(s, s); cp_commit(); }

    float acc[4][4][4];
#pragma unroll
    for (int i = 0; i < 4; i++)
#pragma unroll
        for (int j = 0; j < 4; j++)
#pragma unroll
            for (int k = 0; k < 4; k++) acc[i][j][k] = 0.f;

    // per-lane ldmatrix row/chunk components
    const int arow = wm * 64 + (lane & 15);      // + mi*16
    const int akc  = lane >> 4;                  // + ks*2
    const int brow = wn * 32 + (lane & 7) + ((lane >> 4) << 3);  // + bp*16
    const int bkc  = (lane >> 3) & 1;            // + ks*2

    for (int t = 0; t < G2_NT; t++) {
        cp_wait2();           // oldest group (tile t) retired
        __syncthreads();

        const uint32_t sa = sbase + (t % G2_STAGE) * G2_STAGE_B;
        const uint32_t sb = sa + G2_TILE_B;

#pragma unroll
        for (int ks = 0; ks < 4; ks++) {
            uint32_t af[4][4], bf[2][4];
#pragma unroll
            for (int mi = 0; mi < 4; mi++) {
                const int r  = arow + mi * 16;
                const int kc = ks * 2 + akc;
                ldm_x4(af[mi], sa + r * 128 + (((kc ^ (r & 7))) << 4));
            }
#pragma unroll
            for (int bp = 0; bp < 2; bp++) {
                const int r  = brow + bp * 16;
                const int kc = ks * 2 + bkc;
                ldm_x4(bf[bp], sb + r * 128 + (((kc ^ (r & 7))) << 4));
            }
#pragma unroll
            for (int mi = 0; mi < 4; mi++)
#pragma unroll
                for (int nj = 0; nj < 4; nj++)
                    mma16816(acc[mi][nj], af[mi], &bf[nj >> 1][(nj & 1) * 2]);
        }

        __syncthreads();      // everyone done reading this stage
        if (t + G2_STAGE < G2_NT) load_tile(t % G2_STAGE, t + G2_STAGE);
        cp_commit();          // commit every iter (possibly empty) to keep count
    }

    // ---- epilogue ----
    const int gid = lane >> 2;       // row group 0..7
    const int tig = lane & 3;        // col pair selector
#pragma unroll
    for (int mi = 0; mi < 4; mi++) {
        const int r0 = bm + wm * 64 + mi * 16 + gid;
#pragma unroll
        for (int nj = 0; nj < 4; nj++) {
            const int col = bn + wn * 32 + nj * 8 + tig * 2;
            *(float2*)(C + (size_t)r0 * BB + col)       = make_float2(acc[mi][nj][0], acc[mi][nj][1]);
            *(float2*)(C + (size_t)(r0 + 8) * BB + col) = make_float2(acc[mi][nj][2], acc[mi][nj][3]);
        }
    }
}

// ---------------------------------------------------------------------------
// Pass 1 of max-score alignment: one WARP per (b, j).
// ---------------------------------------------------------------------------
__global__ __launch_bounds__(256)
void scores_kernel(const float* __restrict__ V)
{
    const int gw   = (blockIdx.x * 256 + threadIdx.x) >> 5;
    const int lane = threadIdx.x & 31;
    if (gw >= BB * NPATCH) return;
    const int b = gw / NPATCH;
    const int j = gw - b * NPATCH;

    const float4* v = (const float4*)(V + ((size_t)b * NPATCH + j) * DD);
    const float4* t = (const float4*)(g_t + (size_t)b * DD);

    float d = 0.f, n = 0.f;
#pragma unroll
    for (int s = 0; s < 8; s++) {
        float4 a = v[lane + 32 * s];
        float4 c = t[lane + 32 * s];
        d += a.x * c.x + a.y * c.y + a.z * c.z + a.w * c.w;
        n += a.x * a.x + a.y * a.y + a.z * a.z + a.w * a.w;
    }
#pragma unroll
    for (int o = 16; o; o >>= 1) {
        d += __shfl_xor_sync(0xffffffffu, d, o);
        n += __shfl_xor_sync(0xffffffffu, n, o);
    }
    if (lane == 0)
        g_scores[gw] = d * rsqrtf(fmaxf(n, 1e-24f));
}

// ---------------------------------------------------------------------------
// Pass 2: per-b argmax (first-max tie-break) + gather + normalize.
// ---------------------------------------------------------------------------
__global__ __launch_bounds__(256)
void select_kernel(const float* __restrict__ V)
{
    const int b   = blockIdx.x;
    const int tid = threadIdx.x;

    float best = -3.402823e38f;
    int   bj   = NPATCH;
    const float* sc = g_scores + (size_t)b * NPATCH;
    for (int j = tid; j < NPATCH; j += 256) {
        float s = sc[j];
        if (s > best || (s == best && j < bj)) { best = s; bj = j; }
    }
#pragma unroll
    for (int o = 16; o; o >>= 1) {
        float ob = __shfl_xor_sync(0xffffffffu, best, o);
        int   oj = __shfl_xor_sync(0xffffffffu, bj, o);
        if (ob > best || (ob == best && oj < bj)) { best = ob; bj = oj; }
    }
    __shared__ float rb[8];
    __shared__ int   rj[8];
    if ((tid & 31) == 0) { rb[tid >> 5] = best; rj[tid >> 5] = bj; }
    __syncthreads();
    best = rb[0]; bj = rj[0];
#pragma unroll
    for (int w = 1; w < 8; w++) {
        float ob = rb[w]; int oj = rj[w];
        if (ob > best || (ob == best && oj < bj)) { best = ob; bj = oj; }
    }

    const float4* v = (const float4*)(V + ((size_t)b * NPATCH + bj) * DD);
    float4 a = v[tid];
    float s = a.x * a.x + a.y * a.y + a.z * a.z + a.w * a.w;
#pragma unroll
    for (int o = 16; o; o >>= 1) s += __shfl_xor_sync(0xffffffffu, s, o);
    __shared__ float rn[8];
    if ((tid & 31) == 0) rn[tid >> 5] = s;
    __syncthreads();
    float tot = rn[0] + rn[1] + rn[2] + rn[3] + rn[4] + rn[5] + rn[6] + rn[7];
    float scale = rsqrtf(fmaxf(tot, 1e-24f));
    a.x *= scale; a.y *= scale; a.z *= scale; a.w *= scale;
    ((float4*)(g_vsel + (size_t)b * DD))[tid] = a;
}

// ---------------------------------------------------------------------------
// Launch.  Inputs (metadata order):
//   d_in[0] visual [2048,196,1024] f32 ; d_in[1] textual [2048,512] f32
//   d_in[2] W [1024,512] f32           ; d_in[3] b [1024] f32
// d_out: [2048,2048] f32
// ---------------------------------------------------------------------------
extern "C" void kernel_launch(void* const* d_in, const int* in_sizes, int n_in,
                              void* d_out, int out_size)
{
    const float* visual  = (const float*)d_in[0];
    const float* textual = (const float*)d_in[1];
    const float* W       = (const float*)d_in[2];
    const float* bias    = (const float*)d_in[3];
    float* out = (float*)d_out;

    float *t_ptr = nullptr, *vsel_ptr = nullptr;
    __nv_bfloat16 *a3_ptr = nullptr, *b3_ptr = nullptr;
    cudaGetSymbolAddress((void**)&t_ptr, g_t);
    cudaGetSymbolAddress((void**)&vsel_ptr, g_vsel);
    cudaGetSymbolAddress((void**)&a3_ptr, g_A3);
    cudaGetSymbolAddress((void**)&b3_ptr, g_B3);

    cudaFuncSetAttribute(gemm2_mma, cudaFuncAttributeMaxDynamicSharedMemorySize, G2_SMEM);

    // 1) t_raw = tanh(textual @ W^T + b)
    gemm_tanh<<<dim3(DD / 128, BB / 128), 256>>>(textual, W, bias, t_ptr, DC);
    // 2) t = l2norm(t_raw)
    normalize_rows<<<BB, 256>>>(t_ptr);
    // 3) split t -> A3
    prep_split<<<(BB * DD / 2) / 256, 256>>>(t_ptr, a3_ptr, 0);
    // 4) scores (HBM-bound streaming pass over V)
    {
        const int nwarps  = BB * NPATCH;
        const int nblocks = (nwarps * 32 + 255) / 256;
        scores_kernel<<<nblocks, 256>>>(visual);
    }
    // 5) per-b argmax + gather + normalize
    select_kernel<<<BB, 256>>>(visual);
    // 6) split vsel -> B3
    prep_split<<<(BB * DD / 2) / 256, 256>>>(vsel_ptr, b3_ptr, 1);
    // 7) out = t @ vsel^T on tensor cores (bf16 3-term split, fp32 accum)
    gemm2_mma<<<dim3(BB / 128, BB / 128), 256, G2_SMEM>>>(a3_ptr, b3_ptr, out);
}

// round 8
// speedup vs baseline: 1.2925x; 1.0054x over previous
#include <cuda_runtime.h>
#include <cuda_bf16.h>
#include <cstdint>

// Problem constants (fixed by setup_inputs)
#define BB      2048   // batch
#define NPATCH  196    // patches
#define DD      1024   // dino dim
#define DC      512    // clip dim
#define KAUG    3072   // augmented K for 3-term bf16 split GEMM

// Scratch (allocation-free rule: __device__ globals)
__device__ float g_t[(size_t)BB * DD];          // projected+tanh+normalized text emb
__device__ float g_vsel[(size_t)BB * DD];       // selected+normalized visual emb
__device__ float g_scores[(size_t)BB * NPATCH]; // per-(b,j) cosine scores
__device__ __align__(16) __nv_bfloat16 g_A3[(size_t)BB * KAUG]; // [Th | Tl | Th]
__device__ __align__(16) __nv_bfloat16 g_B3[(size_t)BB * KAUG]; // [Vh | Vh | Vl]

// ---------------------------------------------------------------------------
// Packed f32x2 helpers (for GEMM1)
// ---------------------------------------------------------------------------
__device__ __forceinline__ unsigned long long dup2(float x) {
    unsigned long long r;
    unsigned int u = __float_as_uint(x);
    asm("mov.b64 %0, {%1, %1};" : "=l"(r) : "r"(u));
    return r;
}
__device__ __forceinline__ void fma2(unsigned long long& d,
                                     unsigned long long a, unsigned long long b) {
    asm("fma.rn.f32x2 %0, %1, %2, %0;" : "+l"(d) : "l"(a), "l"(b));
}
__device__ __forceinline__ void unpack2(unsigned long long v, float& lo, float& hi) {
    unsigned int l, h;
    asm("mov.b64 {%0, %1}, %2;" : "=r"(l), "=r"(h) : "l"(v));
    lo = __uint_as_float(l); hi = __uint_as_float(h);
}

// ---------------------------------------------------------------------------
// GEMM1: t_raw = tanh(textual @ W^T + b)   (FFMA2 path; K=512, small)
// ---------------------------------------------------------------------------
__global__ __launch_bounds__(256, 2)
void gemm_tanh(const float* __restrict__ A, const float* __restrict__ Bm,
               const float* __restrict__ bias, float* __restrict__ C, int K)
{
    __shared__ float As[16][128];
    __shared__ float Bs[16][128];

    const int tid = threadIdx.x;
    const int bm  = blockIdx.y * 128;
    const int bn  = blockIdx.x * 128;
    const int N   = gridDim.x * 128;
    const int tx  = tid & 15;
    const int ty  = tid >> 4;
    const int lr = tid >> 2;
    const int lc = (tid & 3) * 4;

    unsigned long long acc2[8][4];
#pragma unroll
    for (int i = 0; i < 8; i++)
#pragma unroll
        for (int j = 0; j < 4; j++) acc2[i][j] = 0ULL;

    const float* Aptr = A + (size_t)bm * K;
    const float* Bptr = Bm + (size_t)bn * K;

    for (int k0 = 0; k0 < K; k0 += 16) {
#pragma unroll
        for (int h = 0; h < 2; h++) {
            const int row = lr + h * 64;
            float4 a = *(const float4*)(Aptr + (size_t)row * K + k0 + lc);
            As[lc + 0][row] = a.x; As[lc + 1][row] = a.y;
            As[lc + 2][row] = a.z; As[lc + 3][row] = a.w;
            float4 b = *(const float4*)(Bptr + (size_t)row * K + k0 + lc);
            Bs[lc + 0][row] = b.x; Bs[lc + 1][row] = b.y;
            Bs[lc + 2][row] = b.z; Bs[lc + 3][row] = b.w;
        }
        __syncthreads();

#pragma unroll
        for (int k = 0; k < 16; k++) {
            float af[8];
            *(float4*)&af[0] = *(const float4*)&As[k][ty * 8];
            *(float4*)&af[4] = *(const float4*)&As[k][ty * 8 + 4];
            unsigned long long bf2[4];
            ulonglong2 b01 = *(const ulonglong2*)&Bs[k][tx * 8];
            ulonglong2 b23 = *(const ulonglong2*)&Bs[k][tx * 8 + 4];
            bf2[0] = b01.x; bf2[1] = b01.y; bf2[2] = b23.x; bf2[3] = b23.y;
            unsigned long long aa[8];
#pragma unroll
            for (int i = 0; i < 8; i++) aa[i] = dup2(af[i]);
#pragma unroll
            for (int i = 0; i < 8; i++)
#pragma unroll
                for (int j = 0; j < 4; j++)
                    fma2(acc2[i][j], aa[i], bf2[j]);
        }
        __syncthreads();
    }

#pragma unroll
    for (int i = 0; i < 8; i++) {
        float* Crow = C + (size_t)(bm + ty * 8 + i) * N + bn + tx * 8;
        float v[8];
#pragma unroll
        for (int j = 0; j < 4; j++) unpack2(acc2[i][j], v[2 * j], v[2 * j + 1]);
#pragma unroll
        for (int j = 0; j < 8; j++) v[j] = tanhf(v[j] + bias[bn + tx * 8 + j]);
        *(float4*)(Crow + 0) = make_float4(v[0], v[1], v[2], v[3]);
        *(float4*)(Crow + 4) = make_float4(v[4], v[5], v[6], v[7]);
    }
}

// ---------------------------------------------------------------------------
// In-place row L2 normalization of X[rows, DD].  One block per row.
// ---------------------------------------------------------------------------
__global__ __launch_bounds__(256)
void normalize_rows(float* __restrict__ X)
{
    const int row = blockIdx.x;
    const int tid = threadIdx.x;
    float4* p = (float4*)(X + (size_t)row * DD);
    float4 a = p[tid];
    float s = a.x * a.x + a.y * a.y + a.z * a.z + a.w * a.w;
#pragma unroll
    for (int o = 16; o; o >>= 1) s += __shfl_xor_sync(0xffffffffu, s, o);
    __shared__ float red[8];
    if ((tid & 31) == 0) red[tid >> 5] = s;
    __syncthreads();
    float tot = red[0] + red[1] + red[2] + red[3] +
                red[4] + red[5] + red[6] + red[7];
    float scale = rsqrtf(fmaxf(tot, 1e-24f));
    a.x *= scale; a.y *= scale; a.z *= scale; a.w *= scale;
    p[tid] = a;
}

// ---------------------------------------------------------------------------
// 3-term bf16 split prep: X[2048,1024] f32 -> Y[2048,3072] bf16.
// mode 0 (A side): segments [hi, lo, hi].  mode 1 (B side): [hi, hi, lo].
// Pairing gives ah*bh + al*bh + ah*bl  (al*bl ~ 2^-18 dropped).
// ---------------------------------------------------------------------------
__global__ __launch_bounds__(256)
void prep_split(const float* __restrict__ X, __nv_bfloat16* __restrict__ Y, int mode)
{
    const int i = blockIdx.x * 256 + threadIdx.x;   // over BB * DD/2 pairs
    const int row = i >> 9;
    const int p   = i & 511;
    float2 x = *(const float2*)(X + (size_t)row * DD + p * 2);
    __nv_bfloat16 h0 = __float2bfloat16(x.x), h1 = __float2bfloat16(x.y);
    __nv_bfloat16 l0 = __float2bfloat16(x.x - __bfloat162float(h0));
    __nv_bfloat16 l1 = __float2bfloat16(x.y - __bfloat162float(h1));
    __nv_bfloat162 hi; hi.x = h0; hi.y = h1;
    __nv_bfloat162 lo; lo.x = l0; lo.y = l1;
    __nv_bfloat162* yr = (__nv_bfloat162*)(Y + (size_t)row * KAUG);
    yr[p] = hi;
    yr[512 + p]  = mode ? hi : lo;
    yr[1024 + p] = mode ? lo : hi;
}

// ===========================================================================
// GEMM2 on tensor cores via mma.sync (arch-agnostic HMMA path):
// C[2048,2048] = A3[2048,3072] @ B3[2048,3072]^T, bf16 in, fp32 accum.
// CTA 128x128, BK=64, 8 warps (warp tile 64m x 32n), 3-stage cp.async,
// XOR-swizzled SMEM (16B chunk ^ (row&7)) -> conflict-free ldmatrix.
// ===========================================================================
#define G2_BK     64
#define G2_NT     (KAUG / G2_BK)    // 48 tiles
#define G2_STAGE  3
#define G2_TILE_B 16384u            // 128 rows * 128 bytes (one matrix)
#define G2_STAGE_B 32768u           // A + B
#define G2_SMEM   (G2_STAGE * G2_STAGE_B)  // 96 KB

__device__ __forceinline__ void cp_async16(uint32_t saddr, const void* gaddr) {
    asm volatile("cp.async.cg.shared.global [%0], [%1], 16;" :: "r"(saddr), "l"(gaddr) : "memory");
}
__device__ __forceinline__ void cp_commit() {
    asm volatile("cp.async.commit_group;" ::: "memory");
}
__device__ __forceinline__ void cp_wait2() {
    asm volatile("cp.async.wait_group 2;" ::: "memory");
}
__device__ __forceinline__ void ldm_x4(uint32_t* r, uint32_t addr) {
    asm volatile("ldmatrix.sync.aligned.m8n8.x4.shared.b16 {%0,%1,%2,%3}, [%4];"
                 : "=r"(r[0]), "=r"(r[1]), "=r"(r[2]), "=r"(r[3]) : "r"(addr));
}
__device__ __forceinline__ void mma16816(float* c, const uint32_t* a, const uint32_t* b) {
    asm volatile("mma.sync.aligned.m16n8k16.row.col.f32.bf16.bf16.f32 "
                 "{%0,%1,%2,%3}, {%4,%5,%6,%7}, {%8,%9}, {%0,%1,%2,%3};"
                 : "+f"(c[0]), "+f"(c[1]), "+f"(c[2]), "+f"(c[3])
                 : "r"(a[0]), "r"(a[1]), "r"(a[2]), "r"(a[3]), "r"(b[0]), "r"(b[1]));
}
__device__ __forceinline__ uint32_t smem_u32(const void* p) {
    uint32_t a;
    asm("{ .reg .u64 t; cvta.to.shared.u64 t, %1; cvt.u32.u64 %0, t; }" : "=r"(a) : "l"(p));
    return a;
}

__global__ __launch_bounds__(256)
void gemm2_mma(const __nv_bfloat16* __restrict__ A3,
               const __nv_bfloat16* __restrict__ B3,
               float* __restrict__ C)
{
    extern __shared__ char smem[];
    const uint32_t sbase = smem_u32(smem);
    const int tid  = threadIdx.x;
    const int lane = tid & 31;
    const int wid  = tid >> 5;
    const int wm   = wid & 1;          // 2 m-tiles of 64
    const int wn   = wid >> 1;         // 4 n-tiles of 32
    const int bm   = blockIdx.y * 128;
    const int bn   = blockIdx.x * 128;

    // ---- gmem -> smem tile loader (thread t: row t/2, 4 chunks of 16B) ----
    const int ldrow = tid >> 1;            // 0..127
    const int ldcb  = (tid & 1) * 4;       // chunk base 0 or 4
    const __nv_bfloat16* Agl = A3 + (size_t)(bm + ldrow) * KAUG;
    const __nv_bfloat16* Bgl = B3 + (size_t)(bn + ldrow) * KAUG;
    const uint32_t ldswz = ldrow * 128;    // byte row base

    auto load_tile = [&](int stage, int t) {
        const uint32_t sa = sbase + stage * G2_STAGE_B + ldswz;
        const uint32_t sb = sa + G2_TILE_B;
        const __nv_bfloat16* ga = Agl + t * G2_BK + ldcb * 8;
        const __nv_bfloat16* gb = Bgl + t * G2_BK + ldcb * 8;
#pragma unroll
        for (int j = 0; j < 4; j++) {
            const int c = ldcb + j;
            const uint32_t ph = (uint32_t)((c ^ (ldrow & 7)) << 4);
            cp_async16(sa + ph, ga + j * 8);
            cp_async16(sb + ph, gb + j * 8);
        }
    };

    // ---- prologue: fill 3 stages ----
#pragma unroll
    for (int s = 0; s < G2_STAGE; s++) { load_tile(s, s); cp_commit(); }

    float acc[4][4][4];
#pragma unroll
    for (int i = 0; i < 4; i++)
#pragma unroll
        for (int j = 0; j < 4; j++)
#pragma unroll
            for (int k = 0; k < 4; k++) acc[i][j][k] = 0.f;

    // per-lane ldmatrix row/chunk components
    const int arow = wm * 64 + (lane & 15);      // + mi*16
    const int akc  = lane >> 4;                  // + ks*2
    const int brow = wn * 32 + (lane & 7) + ((lane >> 4) << 3);  // + bp*16
    const int bkc  = (lane >> 3) & 1;            // + ks*2

    for (int t = 0; t < G2_NT; t++) {
        cp_wait2();           // oldest group (tile t) retired
        __syncthreads();

        const uint32_t sa = sbase + (t % G2_STAGE) * G2_STAGE_B;
        const uint32_t sb = sa + G2_TILE_B;

#pragma unroll
        for (int ks = 0; ks < 4; ks++) {
            uint32_t af[4][4], bf[2][4];
#pragma unroll
            for (int mi = 0; mi < 4; mi++) {
                const int r  = arow + mi * 16;
                const int kc = ks * 2 + akc;
                ldm_x4(af[mi], sa + r * 128 + (((kc ^ (r & 7))) << 4));
            }
#pragma unroll
            for (int bp = 0; bp < 2; bp++) {
                const int r  = brow + bp * 16;
                const int kc = ks * 2 + bkc;
                ldm_x4(bf[bp], sb + r * 128 + (((kc ^ (r & 7))) << 4));
            }
#pragma unroll
            for (int mi = 0; mi < 4; mi++)
#pragma unroll
                for (int nj = 0; nj < 4; nj++)
                    mma16816(acc[mi][nj], af[mi], &bf[nj >> 1][(nj & 1) * 2]);
        }

        __syncthreads();      // everyone done reading this stage
        if (t + G2_STAGE < G2_NT) load_tile(t % G2_STAGE, t + G2_STAGE);
        cp_commit();          // commit every iter (possibly empty) to keep count
    }

    // ---- epilogue ----
    const int gid = lane >> 2;       // row group 0..7
    const int tig = lane & 3;        // col pair selector
#pragma unroll
    for (int mi = 0; mi < 4; mi++) {
        const int r0 = bm + wm * 64 + mi * 16 + gid;
#pragma unroll
        for (int nj = 0; nj < 4; nj++) {
            const int col = bn + wn * 32 + nj * 8 + tig * 2;
            *(float2*)(C + (size_t)r0 * BB + col)       = make_float2(acc[mi][nj][0], acc[mi][nj][1]);
            *(float2*)(C + (size_t)(r0 + 8) * BB + col) = make_float2(acc[mi][nj][2], acc[mi][nj][3]);
        }
    }
}

// ---------------------------------------------------------------------------
// Pass 1 of max-score alignment: one WARP per (b, j).
// ---------------------------------------------------------------------------
__global__ __launch_bounds__(256)
void scores_kernel(const float* __restrict__ V)
{
    const int gw   = (blockIdx.x * 256 + threadIdx.x) >> 5;
    const int lane = threadIdx.x & 31;
    if (gw >= BB * NPATCH) return;
    const int b = gw / NPATCH;
    const int j = gw - b * NPATCH;

    const float4* v = (const float4*)(V + ((size_t)b * NPATCH + j) * DD);
    const float4* t = (const float4*)(g_t + (size_t)b * DD);

    float d = 0.f, n = 0.f;
#pragma unroll
    for (int s = 0; s < 8; s++) {
        float4 a = v[lane + 32 * s];
        float4 c = t[lane + 32 * s];
        d += a.x * c.x + a.y * c.y + a.z * c.z + a.w * c.w;
        n += a.x * a.x + a.y * a.y + a.z * a.z + a.w * a.w;
    }
#pragma unroll
    for (int o = 16; o; o >>= 1) {
        d += __shfl_xor_sync(0xffffffffu, d, o);
        n += __shfl_xor_sync(0xffffffffu, n, o);
    }
    if (lane == 0)
        g_scores[gw] = d * rsqrtf(fmaxf(n, 1e-24f));
}

// ---------------------------------------------------------------------------
// Pass 2: per-b argmax (first-max tie-break) + gather + normalize.
// ---------------------------------------------------------------------------
__global__ __launch_bounds__(256)
void select_kernel(const float* __restrict__ V)
{
    const int b   = blockIdx.x;
    const int tid = threadIdx.x;

    float best = -3.402823e38f;
    int   bj   = NPATCH;
    const float* sc = g_scores + (size_t)b * NPATCH;
    for (int j = tid; j < NPATCH; j += 256) {
        float s = sc[j];
        if (s > best || (s == best && j < bj)) { best = s; bj = j; }
    }
#pragma unroll
    for (int o = 16; o; o >>= 1) {
        float ob = __shfl_xor_sync(0xffffffffu, best, o);
        int   oj = __shfl_xor_sync(0xffffffffu, bj, o);
        if (ob > best || (ob == best && oj < bj)) { best = ob; bj = oj; }
    }
    __shared__ float rb[8];
    __shared__ int   rj[8];
    if ((tid & 31) == 0) { rb[tid >> 5] = best; rj[tid >> 5] = bj; }
    __syncthreads();
    best = rb[0]; bj = rj[0];
#pragma unroll
    for (int w = 1; w < 8; w++) {
        float ob = rb[w]; int oj = rj[w];
        if (ob > best || (ob == best && oj < bj)) { best = ob; bj = oj; }
    }

    const float4* v = (const float4*)(V + ((size_t)b * NPATCH + bj) * DD);
    float4 a = v[tid];
    float s = a.x * a.x + a.y * a.y + a.z * a.z + a.w * a.w;
#pragma unroll
    for (int o = 16; o; o >>= 1) s += __shfl_xor_sync(0xffffffffu, s, o);
    __shared__ float rn[8];
    if ((tid & 31) == 0) rn[tid >> 5] = s;
    __syncthreads();
    float tot = rn[0] + rn[1] + rn[2] + rn[3] + rn[4] + rn[5] + rn[6] + rn[7];
    float scale = rsqrtf(fmaxf(tot, 1e-24f));
    a.x *= scale; a.y *= scale; a.z *= scale; a.w *= scale;
    ((float4*)(g_vsel + (size_t)b * DD))[tid] = a;
}

// ---------------------------------------------------------------------------
// Launch.  Inputs (metadata order):
//   d_in[0] visual [2048,196,1024] f32 ; d_in[1] textual [2048,512] f32
//   d_in[2] W [1024,512] f32           ; d_in[3] b [1024] f32
// d_out: [2048,2048] f32
// ---------------------------------------------------------------------------
extern "C" void kernel_launch(void* const* d_in, const int* in_sizes, int n_in,
                              void* d_out, int out_size)
{
    const float* visual  = (const float*)d_in[0];
    const float* textual = (const float*)d_in[1];
    const float* W       = (const float*)d_in[2];
    const float* bias    = (const float*)d_in[3];
    float* out = (float*)d_out;

    float *t_ptr = nullptr, *vsel_ptr = nullptr;
    __nv_bfloat16 *a3_ptr = nullptr, *b3_ptr = nullptr;
    cudaGetSymbolAddress((void**)&t_ptr, g_t);
    cudaGetSymbolAddress((void**)&vsel_ptr, g_vsel);
    cudaGetSymbolAddress((void**)&a3_ptr, g_A3);
    cudaGetSymbolAddress((void**)&b3_ptr, g_B3);

    cudaFuncSetAttribute(gemm2_mma, cudaFuncAttributeMaxDynamicSharedMemorySize, G2_SMEM);

    // 1) t_raw = tanh(textual @ W^T + b)
    gemm_tanh<<<dim3(DD / 128, BB / 128), 256>>>(textual, W, bias, t_ptr, DC);
    // 2) t = l2norm(t_raw)
    normalize_rows<<<BB, 256>>>(t_ptr);
    // 3) split t -> A3
    prep_split<<<(BB * DD / 2) / 256, 256>>>(t_ptr, a3_ptr, 0);
    // 4) scores (HBM-bound streaming pass over V)
    {
        const int nwarps  = BB * NPATCH;
        const int nblocks = (nwarps * 32 + 255) / 256;
        scores_kernel<<<nblocks, 256>>>(visual);
    }
    // 5) per-b argmax + gather + normalize
    select_kernel<<<BB, 256>>>(visual);
    // 6) split vsel -> B3
    prep_split<<<(BB * DD / 2) / 256, 256>>>(vsel_ptr, b3_ptr, 1);
    // 7) out = t @ vsel^T on tensor cores (bf16 3-term split, fp32 accum)
    gemm2_mma<<<dim3(BB / 128, BB / 128), 256, G2_SMEM>>>(a3_ptr, b3_ptr, out);
}

// round 9
// speedup vs baseline: 1.2926x; 1.0001x over previous
#include <cuda_runtime.h>
#include <cuda_bf16.h>
#include <cstdint>

// Problem constants (fixed by setup_inputs)
#define BB      2048   // batch
#define NPATCH  196    // patches
#define DD      1024   // dino dim
#define DC      512    // clip dim
#define KAUG    3072   // augmented K for 3-term bf16 split GEMM

// Scratch (allocation-free rule: __device__ globals)
__device__ float g_t[(size_t)BB * DD];          // projected+tanh+normalized text emb
__device__ float g_vsel[(size_t)BB * DD];       // selected+normalized visual emb
__device__ float g_scores[(size_t)BB * NPATCH]; // per-(b,j) cosine scores
__device__ __align__(16) __nv_bfloat16 g_A3[(size_t)BB * KAUG]; // [Th | Tl | Th]
__device__ __align__(16) __nv_bfloat16 g_B3[(size_t)BB * KAUG]; // [Vh | Vh | Vl]

// ---------------------------------------------------------------------------
// Packed f32x2 helpers (for GEMM1)
// ---------------------------------------------------------------------------
__device__ __forceinline__ unsigned long long dup2(float x) {
    unsigned long long r;
    unsigned int u = __float_as_uint(x);
    asm("mov.b64 %0, {%1, %1};" : "=l"(r) : "r"(u));
    return r;
}
__device__ __forceinline__ void fma2(unsigned long long& d,
                                     unsigned long long a, unsigned long long b) {
    asm("fma.rn.f32x2 %0, %1, %2, %0;" : "+l"(d) : "l"(a), "l"(b));
}
__device__ __forceinline__ void unpack2(unsigned long long v, float& lo, float& hi) {
    unsigned int l, h;
    asm("mov.b64 {%0, %1}, %2;" : "=r"(l), "=r"(h) : "l"(v));
    lo = __uint_as_float(l); hi = __uint_as_float(h);
}

// ---------------------------------------------------------------------------
// GEMM1: t_raw = tanh(textual @ W^T + b)   (FFMA2 path; K=512, small)
// ---------------------------------------------------------------------------
__global__ __launch_bounds__(256, 2)
void gemm_tanh(const float* __restrict__ A, const float* __restrict__ Bm,
               const float* __restrict__ bias, float* __restrict__ C, int K)
{
    __shared__ float As[16][128];
    __shared__ float Bs[16][128];

    const int tid = threadIdx.x;
    const int bm  = blockIdx.y * 128;
    const int bn  = blockIdx.x * 128;
    const int N   = gridDim.x * 128;
    const int tx  = tid & 15;
    const int ty  = tid >> 4;
    const int lr = tid >> 2;
    const int lc = (tid & 3) * 4;

    unsigned long long acc2[8][4];
#pragma unroll
    for (int i = 0; i < 8; i++)
#pragma unroll
        for (int j = 0; j < 4; j++) acc2[i][j] = 0ULL;

    const float* Aptr = A + (size_t)bm * K;
    const float* Bptr = Bm + (size_t)bn * K;

    for (int k0 = 0; k0 < K; k0 += 16) {
#pragma unroll
        for (int h = 0; h < 2; h++) {
            const int row = lr + h * 64;
            float4 a = *(const float4*)(Aptr + (size_t)row * K + k0 + lc);
            As[lc + 0][row] = a.x; As[lc + 1][row] = a.y;
            As[lc + 2][row] = a.z; As[lc + 3][row] = a.w;
            float4 b = *(const float4*)(Bptr + (size_t)row * K + k0 + lc);
            Bs[lc + 0][row] = b.x; Bs[lc + 1][row] = b.y;
            Bs[lc + 2][row] = b.z; Bs[lc + 3][row] = b.w;
        }
        __syncthreads();

#pragma unroll
        for (int k = 0; k < 16; k++) {
            float af[8];
            *(float4*)&af[0] = *(const float4*)&As[k][ty * 8];
            *(float4*)&af[4] = *(const float4*)&As[k][ty * 8 + 4];
            unsigned long long bf2[4];
            ulonglong2 b01 = *(const ulonglong2*)&Bs[k][tx * 8];
            ulonglong2 b23 = *(const ulonglong2*)&Bs[k][tx * 8 + 4];
            bf2[0] = b01.x; bf2[1] = b01.y; bf2[2] = b23.x; bf2[3] = b23.y;
            unsigned long long aa[8];
#pragma unroll
            for (int i = 0; i < 8; i++) aa[i] = dup2(af[i]);
#pragma unroll
            for (int i = 0; i < 8; i++)
#pragma unroll
                for (int j = 0; j < 4; j++)
                    fma2(acc2[i][j], aa[i], bf2[j]);
        }
        __syncthreads();
    }

#pragma unroll
    for (int i = 0; i < 8; i++) {
        float* Crow = C + (size_t)(bm + ty * 8 + i) * N + bn + tx * 8;
        float v[8];
#pragma unroll
        for (int j = 0; j < 4; j++) unpack2(acc2[i][j], v[2 * j], v[2 * j + 1]);
#pragma unroll
        for (int j = 0; j < 8; j++) v[j] = tanhf(v[j] + bias[bn + tx * 8 + j]);
        *(float4*)(Crow + 0) = make_float4(v[0], v[1], v[2], v[3]);
        *(float4*)(Crow + 4) = make_float4(v[4], v[5], v[6], v[7]);
    }
}

// ---------------------------------------------------------------------------
// In-place row L2 normalization of X[rows, DD].  One block per row.
// ---------------------------------------------------------------------------
__global__ __launch_bounds__(256)
void normalize_rows(float* __restrict__ X)
{
    const int row = blockIdx.x;
    const int tid = threadIdx.x;
    float4* p = (float4*)(X + (size_t)row * DD);
    float4 a = p[tid];
    float s = a.x * a.x + a.y * a.y + a.z * a.z + a.w * a.w;
#pragma unroll
    for (int o = 16; o; o >>= 1) s += __shfl_xor_sync(0xffffffffu, s, o);
    __shared__ float red[8];
    if ((tid & 31) == 0) red[tid >> 5] = s;
    __syncthreads();
    float tot = red[0] + red[1] + red[2] + red[3] +
                red[4] + red[5] + red[6] + red[7];
    float scale = rsqrtf(fmaxf(tot, 1e-24f));
    a.x *= scale; a.y *= scale; a.z *= scale; a.w *= scale;
    p[tid] = a;
}

// ---------------------------------------------------------------------------
// 3-term bf16 split prep: X[2048,1024] f32 -> Y[2048,3072] bf16.
// mode 0 (A side): segments [hi, lo, hi].  mode 1 (B side): [hi, hi, lo].
// Pairing gives ah*bh + al*bh + ah*bl  (al*bl ~ 2^-18 dropped).
// ---------------------------------------------------------------------------
__global__ __launch_bounds__(256)
void prep_split(const float* __restrict__ X, __nv_bfloat16* __restrict__ Y, int mode)
{
    const int i = blockIdx.x * 256 + threadIdx.x;   // over BB * DD/2 pairs
    const int row = i >> 9;
    const int p   = i & 511;
    float2 x = *(const float2*)(X + (size_t)row * DD + p * 2);
    __nv_bfloat16 h0 = __float2bfloat16(x.x), h1 = __float2bfloat16(x.y);
    __nv_bfloat16 l0 = __float2bfloat16(x.x - __bfloat162float(h0));
    __nv_bfloat16 l1 = __float2bfloat16(x.y - __bfloat162float(h1));
    __nv_bfloat162 hi; hi.x = h0; hi.y = h1;
    __nv_bfloat162 lo; lo.x = l0; lo.y = l1;
    __nv_bfloat162* yr = (__nv_bfloat162*)(Y + (size_t)row * KAUG);
    yr[p] = hi;
    yr[512 + p]  = mode ? hi : lo;
    yr[1024 + p] = mode ? lo : hi;
}

// ===========================================================================
// GEMM2 on tensor cores via mma.sync (arch-agnostic HMMA path):
// C[2048,2048] = A3[2048,3072] @ B3[2048,3072]^T, bf16 in, fp32 accum.
// CTA 128x128, BK=64, 8 warps (warp tile 64m x 32n), 3-stage cp.async,
// XOR-swizzled SMEM (16B chunk ^ (row&7)) -> conflict-free ldmatrix.
// ===========================================================================
#define G2_BK     64
#define G2_NT     (KAUG / G2_BK)    // 48 tiles
#define G2_STAGE  3
#define G2_TILE_B 16384u            // 128 rows * 128 bytes (one matrix)
#define G2_STAGE_B 32768u           // A + B
#define G2_SMEM   (G2_STAGE * G2_STAGE_B)  // 96 KB

__device__ __forceinline__ void cp_async16(uint32_t saddr, const void* gaddr) {
    asm volatile("cp.async.cg.shared.global [%0], [%1], 16;" :: "r"(saddr), "l"(gaddr) : "memory");
}
__device__ __forceinline__ void cp_commit() {
    asm volatile("cp.async.commit_group;" ::: "memory");
}
__device__ __forceinline__ void cp_wait2() {
    asm volatile("cp.async.wait_group 2;" ::: "memory");
}
__device__ __forceinline__ void ldm_x4(uint32_t* r, uint32_t addr) {
    asm volatile("ldmatrix.sync.aligned.m8n8.x4.shared.b16 {%0,%1,%2,%3}, [%4];"
                 : "=r"(r[0]), "=r"(r[1]), "=r"(r[2]), "=r"(r[3]) : "r"(addr));
}
__device__ __forceinline__ void mma16816(float* c, const uint32_t* a, const uint32_t* b) {
    asm volatile("mma.sync.aligned.m16n8k16.row.col.f32.bf16.bf16.f32 "
                 "{%0,%1,%2,%3}, {%4,%5,%6,%7}, {%8,%9}, {%0,%1,%2,%3};"
                 : "+f"(c[0]), "+f"(c[1]), "+f"(c[2]), "+f"(c[3])
                 : "r"(a[0]), "r"(a[1]), "r"(a[2]), "r"(a[3]), "r"(b[0]), "r"(b[1]));
}
__device__ __forceinline__ uint32_t smem_u32(const void* p) {
    uint32_t a;
    asm("{ .reg .u64 t; cvta.to.shared.u64 t, %1; cvt.u32.u64 %0, t; }" : "=r"(a) : "l"(p));
    return a;
}

__global__ __launch_bounds__(256)
void gemm2_mma(const __nv_bfloat16* __restrict__ A3,
               const __nv_bfloat16* __restrict__ B3,
               float* __restrict__ C)
{
    extern __shared__ char smem[];
    const uint32_t sbase = smem_u32(smem);
    const int tid  = threadIdx.x;
    const int lane = tid & 31;
    const int wid  = tid >> 5;
    const int wm   = wid & 1;          // 2 m-tiles of 64
    const int wn   = wid >> 1;         // 4 n-tiles of 32
    const int bm   = blockIdx.y * 128;
    const int bn   = blockIdx.x * 128;

    // ---- gmem -> smem tile loader (thread t: row t/2, 4 chunks of 16B) ----
    const int ldrow = tid >> 1;            // 0..127
    const int ldcb  = (tid & 1) * 4;       // chunk base 0 or 4
    const __nv_bfloat16* Agl = A3 + (size_t)(bm + ldrow) * KAUG;
    const __nv_bfloat16* Bgl = B3 + (size_t)(bn + ldrow) * KAUG;
    const uint32_t ldswz = ldrow * 128;    // byte row base

    auto load_tile = [&](int stage, int t) {
        const uint32_t sa = sbase + stage * G2_STAGE_B + ldswz;
        const uint32_t sb = sa + G2_TILE_B;
        const __nv_bfloat16* ga = Agl + t * G2_BK + ldcb * 8;
        const __nv_bfloat16* gb = Bgl + t * G2_BK + ldcb * 8;
#pragma unroll
        for (int j = 0; j < 4; j++) {
            const int c = ldcb + j;
            const uint32_t ph = (uint32_t)((c ^ (ldrow & 7)) << 4);
            cp_async16(sa + ph, ga + j * 8);
            cp_async16(sb + ph, gb + j * 8);
        }
    };

    // ---- prologue: fill 3 stages ----
#pragma unroll
    for (int s = 0; s < G2_STAGE; s++) { load_tile(s, s); cp_commit(); }

    float acc[4][4][4];
#pragma unroll
    for (int i = 0; i < 4; i++)
#pragma unroll
        for (int j = 0; j < 4; j++)
#pragma unroll
            for (int k = 0; k < 4; k++) acc[i][j][k] = 0.f;

    // per-lane ldmatrix row/chunk components
    const int arow = wm * 64 + (lane & 15);      // + mi*16
    const int akc  = lane >> 4;                  // + ks*2
    const int brow = wn * 32 + (lane & 7) + ((lane >> 4) << 3);  // + bp*16
    const int bkc  = (lane >> 3) & 1;            // + ks*2

    for (int t = 0; t < G2_NT; t++) {
        cp_wait2();           // oldest group (tile t) retired
        __syncthreads();

        const uint32_t sa = sbase + (t % G2_STAGE) * G2_STAGE_B;
        const uint32_t sb = sa + G2_TILE_B;

#pragma unroll
        for (int ks = 0; ks < 4; ks++) {
            uint32_t af[4][4], bf[2][4];
#pragma unroll
            for (int mi = 0; mi < 4; mi++) {
                const int r  = arow + mi * 16;
                const int kc = ks * 2 + akc;
                ldm_x4(af[mi], sa + r * 128 + (((kc ^ (r & 7))) << 4));
            }
#pragma unroll
            for (int bp = 0; bp < 2; bp++) {
                const int r  = brow + bp * 16;
                const int kc = ks * 2 + bkc;
                ldm_x4(bf[bp], sb + r * 128 + (((kc ^ (r & 7))) << 4));
            }
#pragma unroll
            for (int mi = 0; mi < 4; mi++)
#pragma unroll
                for (int nj = 0; nj < 4; nj++)
                    mma16816(acc[mi][nj], af[mi], &bf[nj >> 1][(nj & 1) * 2]);
        }

        __syncthreads();      // everyone done reading this stage
        if (t + G2_STAGE < G2_NT) load_tile(t % G2_STAGE, t + G2_STAGE);
        cp_commit();          // commit every iter (possibly empty) to keep count
    }

    // ---- epilogue ----
    const int gid = lane >> 2;       // row group 0..7
    const int tig = lane & 3;        // col pair selector
#pragma unroll
    for (int mi = 0; mi < 4; mi++) {
        const int r0 = bm + wm * 64 + mi * 16 + gid;
#pragma unroll
        for (int nj = 0; nj < 4; nj++) {
            const int col = bn + wn * 32 + nj * 8 + tig * 2;
            *(float2*)(C + (size_t)r0 * BB + col)       = make_float2(acc[mi][nj][0], acc[mi][nj][1]);
            *(float2*)(C + (size_t)(r0 + 8) * BB + col) = make_float2(acc[mi][nj][2], acc[mi][nj][3]);
        }
    }
}

// ---------------------------------------------------------------------------
// Pass 1 of max-score alignment: one WARP per (b, j).
// ---------------------------------------------------------------------------
__global__ __launch_bounds__(256)
void scores_kernel(const float* __restrict__ V)
{
    const int gw   = (blockIdx.x * 256 + threadIdx.x) >> 5;
    const int lane = threadIdx.x & 31;
    if (gw >= BB * NPATCH) return;
    const int b = gw / NPATCH;
    const int j = gw - b * NPATCH;

    const float4* v = (const float4*)(V + ((size_t)b * NPATCH + j) * DD);
    const float4* t = (const float4*)(g_t + (size_t)b * DD);

    float d = 0.f, n = 0.f;
#pragma unroll
    for (int s = 0; s < 8; s++) {
        float4 a = v[lane + 32 * s];
        float4 c = t[lane + 32 * s];
        d += a.x * c.x + a.y * c.y + a.z * c.z + a.w * c.w;
        n += a.x * a.x + a.y * a.y + a.z * a.z + a.w * a.w;
    }
#pragma unroll
    for (int o = 16; o; o >>= 1) {
        d += __shfl_xor_sync(0xffffffffu, d, o);
        n += __shfl_xor_sync(0xffffffffu, n, o);
    }
    if (lane == 0)
        g_scores[gw] = d * rsqrtf(fmaxf(n, 1e-24f));
}

// ---------------------------------------------------------------------------
// Pass 2: per-b argmax (first-max tie-break) + gather + normalize.
// ---------------------------------------------------------------------------
__global__ __launch_bounds__(256)
void select_kernel(const float* __restrict__ V)
{
    const int b   = blockIdx.x;
    const int tid = threadIdx.x;

    float best = -3.402823e38f;
    int   bj   = NPATCH;
    const float* sc = g_scores + (size_t)b * NPATCH;
    for (int j = tid; j < NPATCH; j += 256) {
        float s = sc[j];
        if (s > best || (s == best && j < bj)) { best = s; bj = j; }
    }
#pragma unroll
    for (int o = 16; o; o >>= 1) {
        float ob = __shfl_xor_sync(0xffffffffu, best, o);
        int   oj = __shfl_xor_sync(0xffffffffu, bj, o);
        if (ob > best || (ob == best && oj < bj)) { best = ob; bj = oj; }
    }
    __shared__ float rb[8];
    __shared__ int   rj[8];
    if ((tid & 31) == 0) { rb[tid >> 5] = best; rj[tid >> 5] = bj; }
    __syncthreads();
    best = rb[0]; bj = rj[0];
#pragma unroll
    for (int w = 1; w < 8; w++) {
        float ob = rb[w]; int oj = rj[w];
        if (ob > best || (ob == best && oj < bj)) { best = ob; bj = oj; }
    }

    const float4* v = (const float4*)(V + ((size_t)b * NPATCH + bj) * DD);
    float4 a = v[tid];
    float s = a.x * a.x + a.y * a.y + a.z * a.z + a.w * a.w;
#pragma unroll
    for (int o = 16; o; o >>= 1) s += __shfl_xor_sync(0xffffffffu, s, o);
    __shared__ float rn[8];
    if ((tid & 31) == 0) rn[tid >> 5] = s;
    __syncthreads();
    float tot = rn[0] + rn[1] + rn[2] + rn[3] + rn[4] + rn[5] + rn[6] + rn[7];
    float scale = rsqrtf(fmaxf(tot, 1e-24f));
    a.x *= scale; a.y *= scale; a.z *= scale; a.w *= scale;
    ((float4*)(g_vsel + (size_t)b * DD))[tid] = a;
}

// ---------------------------------------------------------------------------
// Launch.  Inputs (metadata order):
//   d_in[0] visual [2048,196,1024] f32 ; d_in[1] textual [2048,512] f32
//   d_in[2] W [1024,512] f32           ; d_in[3] b [1024] f32
// d_out: [2048,2048] f32
// ---------------------------------------------------------------------------
extern "C" void kernel_launch(void* const* d_in, const int* in_sizes, int n_in,
                              void* d_out, int out_size)
{
    const float* visual  = (const float*)d_in[0];
    const float* textual = (const float*)d_in[1];
    const float* W       = (const float*)d_in[2];
    const float* bias    = (const float*)d_in[3];
    float* out = (float*)d_out;

    float *t_ptr = nullptr, *vsel_ptr = nullptr;
    __nv_bfloat16 *a3_ptr = nullptr, *b3_ptr = nullptr;
    cudaGetSymbolAddress((void**)&t_ptr, g_t);
    cudaGetSymbolAddress((void**)&vsel_ptr, g_vsel);
    cudaGetSymbolAddress((void**)&a3_ptr, g_A3);
    cudaGetSymbolAddress((void**)&b3_ptr, g_B3);

    cudaFuncSetAttribute(gemm2_mma, cudaFuncAttributeMaxDynamicSharedMemorySize, G2_SMEM);

    // 1) t_raw = tanh(textual @ W^T + b)
    gemm_tanh<<<dim3(DD / 128, BB / 128), 256>>>(textual, W, bias, t_ptr, DC);
    // 2) t = l2norm(t_raw)
    normalize_rows<<<BB, 256>>>(t_ptr);
    // 3) split t -> A3
    prep_split<<<(BB * DD / 2) / 256, 256>>>(t_ptr, a3_ptr, 0);
    // 4) scores (HBM-bound streaming pass over V)
    {
        const int nwarps  = BB * NPATCH;
        const int nblocks = (nwarps * 32 + 255) / 256;
        scores_kernel<<<nblocks, 256>>>(visual);
    }
    // 5) per-b argmax + gather + normalize
    select_kernel<<<BB, 256>>>(visual);
    // 6) split vsel -> B3
    prep_split<<<(BB * DD / 2) / 256, 256>>>(vsel_ptr, b3_ptr, 1);
    // 7) out = t @ vsel^T on tensor cores (bf16 3-term split, fp32 accum)
    gemm2_mma<<<dim3(BB / 128, BB / 128), 256, G2_SMEM>>>(a3_ptr, b3_ptr, out);
}